// round 7
// baseline (speedup 1.0000x reference)
#include <cuda_runtime.h>

// Problem dims (fixed): B=8, N=1024, C=256, H=4, D=64
#define Bb   8
#define Nn   1024
#define Cc   256
#define Hh   4
#define Dd   64
#define HD   256               // H*D
#define ROWS (Bb * Nn)         // 8192
#define NEG_SLOPE 0.2f

// Scratch (device globals: allocation-free rule)
__device__ float g_Wx[ROWS * HD];   // 8 MB
__device__ float g_ei[ROWS * Hh];
__device__ float g_ej[ROWS * Hh];

// ---------------------------------------------------------------------------
// Kernel 1: Wx = x @ W  (8192x256 @ 256x256), 128x128 tiles, 8x8 per thread,
// single wave (grid=128), fused e_i/e_j epilogue (2 heads per block).
// ---------------------------------------------------------------------------
__global__ void __launch_bounds__(256) gemm_fused_k(const float* __restrict__ A,
                                                    const float* __restrict__ Bm,
                                                    const float* __restrict__ avec) {
    __shared__ float As[16][132];     // k-major
    __shared__ float Bs[16][132];
    __shared__ float s_ai[128], s_aj[128];   // 2 heads x 64

    const int tid = threadIdx.x;
    const int tx = tid & 15;          // 0..15 -> 8 cols each
    const int ty = tid >> 4;          // 0..15 -> 8 rows each
    const int row0 = blockIdx.x * 128;
    const int col0 = blockIdx.y * 128;

    if (tid < 128) {
        int hl = tid >> 6, d = tid & 63;
        s_ai[tid] = avec[(blockIdx.y * 2 + hl) * 128 + d];
        s_aj[tid] = avec[(blockIdx.y * 2 + hl) * 128 + 64 + d];
    }

    float acc[8][8] = {};

    const int ar = tid >> 1;            // 0..127
    const int ac = (tid & 1) * 8;       // 0 or 8
    const int br = tid >> 4;            // 0..15
    const int bc = (tid & 15) * 8;      // 0..120

    const float* aptr = &A[(size_t)(row0 + ar) * Cc + ac];
    const float* bptr = &Bm[(size_t)br * HD + col0 + bc];

    float4 pa0 = *(const float4*)(aptr);
    float4 pa1 = *(const float4*)(aptr + 4);
    float4 pb0 = *(const float4*)(bptr);
    float4 pb1 = *(const float4*)(bptr + 4);

    for (int k0 = 0; k0 < Cc; k0 += 16) {
        As[ac + 0][ar] = pa0.x; As[ac + 1][ar] = pa0.y;
        As[ac + 2][ar] = pa0.z; As[ac + 3][ar] = pa0.w;
        As[ac + 4][ar] = pa1.x; As[ac + 5][ar] = pa1.y;
        As[ac + 6][ar] = pa1.z; As[ac + 7][ar] = pa1.w;
        *(float4*)&Bs[br][bc] = pb0;
        *(float4*)&Bs[br][bc + 4] = pb1;
        __syncthreads();

        if (k0 + 16 < Cc) {
            pa0 = *(const float4*)(aptr + k0 + 16);
            pa1 = *(const float4*)(aptr + k0 + 20);
            pb0 = *(const float4*)(bptr + (size_t)(k0 + 16) * HD);
            pb1 = *(const float4*)(bptr + (size_t)(k0 + 16) * HD + 4);
        }

#pragma unroll
        for (int kk = 0; kk < 16; kk++) {
            float4 x0 = *(float4*)&As[kk][ty * 8];
            float4 x1 = *(float4*)&As[kk][ty * 8 + 4];
            float4 y0 = *(float4*)&Bs[kk][tx * 8];
            float4 y1 = *(float4*)&Bs[kk][tx * 8 + 4];
            float aa[8] = { x0.x, x0.y, x0.z, x0.w, x1.x, x1.y, x1.z, x1.w };
            float bb[8] = { y0.x, y0.y, y0.z, y0.w, y1.x, y1.y, y1.z, y1.w };
#pragma unroll
            for (int i = 0; i < 8; i++)
#pragma unroll
                for (int j = 0; j < 8; j++)
                    acc[i][j] = fmaf(aa[i], bb[j], acc[i][j]);
        }
        __syncthreads();
    }

    // Store Wx
#pragma unroll
    for (int i = 0; i < 8; i++) {
        float* orow = &g_Wx[(size_t)(row0 + ty * 8 + i) * HD + col0 + tx * 8];
        *(float4*)orow       = make_float4(acc[i][0], acc[i][1], acc[i][2], acc[i][3]);
        *(float4*)(orow + 4) = make_float4(acc[i][4], acc[i][5], acc[i][6], acc[i][7]);
    }

    // Fused e_i / e_j epilogue: this thread's 8 cols live in head (tx>>3)
    const int hl = tx >> 3;                 // 0 or 1
    const int cbase = hl * 64 + (tx & 7) * 8;
    float pi[8], pj[8];
#pragma unroll
    for (int i = 0; i < 8; i++) {
        float si = 0.0f, sj = 0.0f;
#pragma unroll
        for (int j = 0; j < 8; j++) {
            si = fmaf(acc[i][j], s_ai[cbase + j], si);
            sj = fmaf(acc[i][j], s_aj[cbase + j], sj);
        }
        pi[i] = si; pj[i] = sj;
    }
    // reduce across 8-lane segments (tx 0..7 / 8..15)
#pragma unroll
    for (int off = 4; off > 0; off >>= 1) {
#pragma unroll
        for (int i = 0; i < 8; i++) {
            pi[i] += __shfl_down_sync(0xffffffffu, pi[i], off, 8);
            pj[i] += __shfl_down_sync(0xffffffffu, pj[i], off, 8);
        }
    }
    if ((tx & 7) == 0) {
        const int h = blockIdx.y * 2 + hl;
#pragma unroll
        for (int i = 0; i < 8; i++) {
            int row = row0 + ty * 8 + i;
            g_ei[row * Hh + h] = pi[i];
            g_ej[row * Hh + h] = pj[i];
        }
    }
}

// ---------------------------------------------------------------------------
// Kernel 2: sparse masked softmax + float4 gather-accumulate. 1 block per (b,n)
// s_jw[h][k] = { exp-weight for head h, bitcast(j*64) }
// ---------------------------------------------------------------------------
#define KPAD 1036
__global__ void __launch_bounds__(256) attn_k(const float* __restrict__ adj,
                                              float* __restrict__ out) {
    __shared__ float2 s_jw[Hh][KPAD];    // 33.1 KB
    __shared__ int    s_tot[8];
    __shared__ float  s_rsum[8][4];
    __shared__ float  s_acc[4][Hh * 64];

    const int tid  = threadIdx.x;
    const int blk  = blockIdx.x;          // b*N + n
    const int b    = blk >> 10;
    const int n    = blk & 1023;
    const int warp = tid >> 5;
    const int lane = tid & 31;

    // ---- compaction: each thread owns 4 consecutive j; writes j*64 offsets ----
    const float4* arow4 = (const float4*)(adj + (size_t)blk * Nn);
    float4 v = arow4[tid];
    const int j0 = tid * 4;
    unsigned mk = 0;
    if (v.x != 0.0f || j0     == n) mk |= 1u;
    if (v.y != 0.0f || j0 + 1 == n) mk |= 2u;
    if (v.z != 0.0f || j0 + 2 == n) mk |= 4u;
    if (v.w != 0.0f || j0 + 3 == n) mk |= 8u;
    int cnt = __popc(mk);
    int scan = cnt;
#pragma unroll
    for (int off = 1; off < 32; off <<= 1) {
        int t = __shfl_up_sync(0xffffffffu, scan, off);
        if (lane >= off) scan += t;
    }
    if (lane == 31) s_tot[warp] = scan;
    __syncthreads();
    int base = 0, K = 0;
#pragma unroll
    for (int w = 0; w < 8; w++) {
        int t = s_tot[w];
        if (w < warp) base += t;
        K += t;
    }
    int pos0 = base + (scan - cnt);
#pragma unroll
    for (int q = 0; q < 4; q++) {
        if (mk & (1u << q)) {
            float jf = __int_as_float((j0 + q) * 64);
            s_jw[0][pos0].y = jf;
            s_jw[1][pos0].y = jf;
            s_jw[2][pos0].y = jf;
            s_jw[3][pos0].y = jf;
            pos0++;
        }
    }
    __syncthreads();

    // ---- fused score + exp + sum (no max-subtract: |s| <= ~10, fp32-safe) ----
    float4 eiv = *(const float4*)&g_ei[blk * Hh];
    const float4* ej4 = (const float4*)g_ej;
    float lsum[4] = {};
    for (int k = tid; k < K; k += 256) {
        int j = __float_as_int(s_jw[0][k].y) >> 6;
        float4 ejv = __ldg(&ej4[(b << 10) + j]);
        float s0 = eiv.x + ejv.x, s1 = eiv.y + ejv.y;
        float s2 = eiv.z + ejv.z, s3 = eiv.w + ejv.w;
        s0 = s0 > 0.0f ? s0 : NEG_SLOPE * s0;
        s1 = s1 > 0.0f ? s1 : NEG_SLOPE * s1;
        s2 = s2 > 0.0f ? s2 : NEG_SLOPE * s2;
        s3 = s3 > 0.0f ? s3 : NEG_SLOPE * s3;
        float w0 = __expf(s0), w1 = __expf(s1);
        float w2 = __expf(s2), w3 = __expf(s3);
        s_jw[0][k].x = w0; s_jw[1][k].x = w1;
        s_jw[2][k].x = w2; s_jw[3][k].x = w3;
        lsum[0] += w0; lsum[1] += w1; lsum[2] += w2; lsum[3] += w3;
    }
#pragma unroll
    for (int off = 16; off > 0; off >>= 1)
#pragma unroll
        for (int h = 0; h < 4; h++)
            lsum[h] += __shfl_xor_sync(0xffffffffu, lsum[h], off);
    if (lane == 0)
#pragma unroll
        for (int h = 0; h < 4; h++) s_rsum[warp][h] = lsum[h];
    __syncthreads();   // orders s_jw weight-writes before gather reads

    // ---- float4 gather: pos owns out floats [4pos,4pos+4), grp splits k ----
    const int pos = tid & 63;
    const int grp = tid >> 6;
    const int hh  = pos >> 4;            // head of this float4
    const float4* wx4 = (const float4*)(g_Wx + (size_t)b * (Nn * HD));
    float4 acc = make_float4(0.f, 0.f, 0.f, 0.f);
    int k = grp;
    for (; k + 12 < K; k += 16) {
        float2 p0 = s_jw[hh][k];
        float2 p1 = s_jw[hh][k + 4];
        float2 p2 = s_jw[hh][k + 8];
        float2 p3 = s_jw[hh][k + 12];
        float4 v0 = __ldg(&wx4[__float_as_int(p0.y) + pos]);
        float4 v1 = __ldg(&wx4[__float_as_int(p1.y) + pos]);
        float4 v2 = __ldg(&wx4[__float_as_int(p2.y) + pos]);
        float4 v3 = __ldg(&wx4[__float_as_int(p3.y) + pos]);
        acc.x = fmaf(p0.x, v0.x, acc.x); acc.y = fmaf(p0.x, v0.y, acc.y);
        acc.z = fmaf(p0.x, v0.z, acc.z); acc.w = fmaf(p0.x, v0.w, acc.w);
        acc.x = fmaf(p1.x, v1.x, acc.x); acc.y = fmaf(p1.x, v1.y, acc.y);
        acc.z = fmaf(p1.x, v1.z, acc.z); acc.w = fmaf(p1.x, v1.w, acc.w);
        acc.x = fmaf(p2.x, v2.x, acc.x); acc.y = fmaf(p2.x, v2.y, acc.y);
        acc.z = fmaf(p2.x, v2.z, acc.z); acc.w = fmaf(p2.x, v2.w, acc.w);
        acc.x = fmaf(p3.x, v3.x, acc.x); acc.y = fmaf(p3.x, v3.y, acc.y);
        acc.z = fmaf(p3.x, v3.z, acc.z); acc.w = fmaf(p3.x, v3.w, acc.w);
    }
    for (; k < K; k += 4) {
        float2 p = s_jw[hh][k];
        float4 vv = __ldg(&wx4[__float_as_int(p.y) + pos]);
        acc.x = fmaf(p.x, vv.x, acc.x); acc.y = fmaf(p.x, vv.y, acc.y);
        acc.z = fmaf(p.x, vv.z, acc.z); acc.w = fmaf(p.x, vv.w, acc.w);
    }
    *(float4*)&s_acc[grp][pos * 4] = acc;
    __syncthreads();

    // ---- cross-group reduce + normalize + store ----
    if (tid < 64) {
        const int h = tid >> 4;
        float4 r = *(float4*)&s_acc[0][tid * 4];
#pragma unroll
        for (int g = 1; g < 4; g++) {
            float4 t = *(float4*)&s_acc[g][tid * 4];
            r.x += t.x; r.y += t.y; r.z += t.z; r.w += t.w;
        }
        float tot = 0.0f;
#pragma unroll
        for (int w = 0; w < 8; w++) tot += s_rsum[w][h];
        float inv = 1.0f / tot;
        r.x *= inv; r.y *= inv; r.z *= inv; r.w *= inv;
        *(float4*)&out[(size_t)blk * HD + tid * 4] = r;
    }
}

// ---------------------------------------------------------------------------
extern "C" void kernel_launch(void* const* d_in, const int* in_sizes, int n_in,
                              void* d_out, int out_size) {
    const float *x = nullptr, *adj = nullptr, *W = nullptr, *a = nullptr;
    for (int i = 0; i < n_in; i++) {
        switch (in_sizes[i]) {
            case Bb * Nn * Cc:  x   = (const float*)d_in[i]; break;  // 2097152
            case Bb * Nn * Nn:  adj = (const float*)d_in[i]; break;  // 8388608
            case Cc * HD:       W   = (const float*)d_in[i]; break;  // 65536
            case Hh * 2 * Dd:   a   = (const float*)d_in[i]; break;  // 512
        }
    }
    float* out = (float*)d_out;

    dim3 ggrid(ROWS / 128, HD / 128);   // 64 x 2 = 128 blocks, single wave
    gemm_fused_k<<<ggrid, 256>>>(x, W, a);
    attn_k<<<ROWS, 256>>>(adj, out);
}

// round 8
// speedup vs baseline: 1.7027x; 1.7027x over previous
#include <cuda_runtime.h>

// Problem dims (fixed): B=8, N=1024, C=256, H=4, D=64
#define Bb   8
#define Nn   1024
#define Cc   256
#define Hh   4
#define Dd   64
#define HD   256               // H*D
#define ROWS (Bb * Nn)         // 8192
#define NEG_SLOPE 0.2f

// Scratch (device globals: allocation-free rule)
__device__ float g_Wx[ROWS * HD];   // 8 MB
__device__ float g_ei[ROWS * Hh];
__device__ float g_ej[ROWS * Hh];

// ---------------------------------------------------------------------------
// Kernel 1: Wx = x @ W  (8192x256 @ 256x256), 128x64 tiles, 8x4 per thread,
// software-pipelined global loads, fused e_i/e_j epilogue (1 head per col-tile)
// (unchanged from the 80.2us baseline)
// ---------------------------------------------------------------------------
__global__ void __launch_bounds__(256) gemm_fused_k(const float* __restrict__ A,
                                                    const float* __restrict__ Bm,
                                                    const float* __restrict__ avec) {
    __shared__ float As[16][132];     // k-major, padded
    __shared__ float Bs[16][68];
    __shared__ float s_ai[64], s_aj[64];

    const int tid = threadIdx.x;
    const int tx = tid & 15;          // 0..15 -> 4 cols each
    const int ty = tid >> 4;          // 0..15 -> 8 rows each
    const int row0 = blockIdx.x * 128;
    const int col0 = blockIdx.y * 64;
    const int h = blockIdx.y;         // head index

    if (tid < 64) {
        s_ai[tid] = avec[h * 128 + tid];
        s_aj[tid] = avec[h * 128 + 64 + tid];
    }

    float acc[8][4] = {};

    const int ar = tid >> 1;
    const int ac = (tid & 1) * 8;
    const int br = tid >> 4;
    const int bc = (tid & 15) * 4;

    const float* aptr = &A[(size_t)(row0 + ar) * Cc + ac];
    const float* bptr = &Bm[(size_t)br * HD + col0 + bc];

    // preload k0 = 0
    float4 a0 = *(const float4*)(aptr);
    float4 a1 = *(const float4*)(aptr + 4);
    float4 bv = *(const float4*)(bptr);

    for (int k0 = 0; k0 < Cc; k0 += 16) {
        As[ac + 0][ar] = a0.x; As[ac + 1][ar] = a0.y;
        As[ac + 2][ar] = a0.z; As[ac + 3][ar] = a0.w;
        As[ac + 4][ar] = a1.x; As[ac + 5][ar] = a1.y;
        As[ac + 6][ar] = a1.z; As[ac + 7][ar] = a1.w;
        *(float4*)&Bs[br][bc] = bv;
        __syncthreads();

        if (k0 + 16 < Cc) {    // prefetch next k-tile during compute
            a0 = *(const float4*)(aptr + k0 + 16);
            a1 = *(const float4*)(aptr + k0 + 20);
            bv = *(const float4*)(bptr + (size_t)(k0 + 16) * HD);
        }

#pragma unroll
        for (int kk = 0; kk < 16; kk++) {
            float4 av0 = *(float4*)&As[kk][ty * 8];
            float4 av1 = *(float4*)&As[kk][ty * 8 + 4];
            float4 bv4 = *(float4*)&Bs[kk][tx * 4];
            float aa[8] = { av0.x, av0.y, av0.z, av0.w, av1.x, av1.y, av1.z, av1.w };
            float bb[4] = { bv4.x, bv4.y, bv4.z, bv4.w };
#pragma unroll
            for (int i = 0; i < 8; i++)
#pragma unroll
                for (int j = 0; j < 4; j++)
                    acc[i][j] = fmaf(aa[i], bb[j], acc[i][j]);
        }
        __syncthreads();
    }

    // Store Wx
#pragma unroll
    for (int i = 0; i < 8; i++) {
        float4 o = make_float4(acc[i][0], acc[i][1], acc[i][2], acc[i][3]);
        *(float4*)&g_Wx[(size_t)(row0 + ty * 8 + i) * HD + col0 + tx * 4] = o;
    }

    // Fused e_i / e_j epilogue
    float pi[8], pj[8];
#pragma unroll
    for (int i = 0; i < 8; i++) {
        float si = 0.0f, sj = 0.0f;
#pragma unroll
        for (int j = 0; j < 4; j++) {
            si = fmaf(acc[i][j], s_ai[tx * 4 + j], si);
            sj = fmaf(acc[i][j], s_aj[tx * 4 + j], sj);
        }
        pi[i] = si; pj[i] = sj;
    }
#pragma unroll
    for (int off = 8; off > 0; off >>= 1) {
#pragma unroll
        for (int i = 0; i < 8; i++) {
            pi[i] += __shfl_down_sync(0xffffffffu, pi[i], off, 16);
            pj[i] += __shfl_down_sync(0xffffffffu, pj[i], off, 16);
        }
    }
    if (tx == 0) {
#pragma unroll
        for (int i = 0; i < 8; i++) {
            int row = row0 + ty * 8 + i;
            g_ei[row * Hh + h] = pi[i];
            g_ej[row * Hh + h] = pj[i];
        }
    }
}

// ---------------------------------------------------------------------------
// Kernel 2: sparse masked softmax + float4 gather-accumulate. 1 block per (b,n)
// Round-5 structure (25KB smem, occ ~90%) + fused score/exp/sum (no max pass)
// + 32-bit gather offsets (s_idx holds j*64).
// ---------------------------------------------------------------------------
__global__ void __launch_bounds__(256) attn_k(const float* __restrict__ adj,
                                              float* __restrict__ out) {
    __shared__ int   s_idx[Nn];          // compacted j*64 offsets (ordered)
    __shared__ float s_w[Nn * Hh];       // [k][h] exp-weights (float4 per k)
    __shared__ int   s_tot[8];
    __shared__ float s_rsum[8][4];
    __shared__ float s_acc[4][Hh * 64];  // [grp][pos*4] partial accumulators

    const int tid  = threadIdx.x;
    const int blk  = blockIdx.x;          // b*N + n
    const int b    = blk >> 10;
    const int n    = blk & 1023;
    const int warp = tid >> 5;
    const int lane = tid & 31;

    // ---- compaction: each thread owns 4 consecutive j ----
    const float4* arow4 = (const float4*)(adj + (size_t)blk * Nn);
    float4 v = arow4[tid];
    const int j0 = tid * 4;
    unsigned mk = 0;
    if (v.x != 0.0f || j0     == n) mk |= 1u;
    if (v.y != 0.0f || j0 + 1 == n) mk |= 2u;
    if (v.z != 0.0f || j0 + 2 == n) mk |= 4u;
    if (v.w != 0.0f || j0 + 3 == n) mk |= 8u;
    int cnt = __popc(mk);
    int scan = cnt;
#pragma unroll
    for (int off = 1; off < 32; off <<= 1) {
        int t = __shfl_up_sync(0xffffffffu, scan, off);
        if (lane >= off) scan += t;
    }
    if (lane == 31) s_tot[warp] = scan;
    __syncthreads();
    int base = 0, K = 0;
#pragma unroll
    for (int w = 0; w < 8; w++) {
        int t = s_tot[w];
        if (w < warp) base += t;
        K += t;
    }
    int pos0 = base + (scan - cnt);
    if (mk & 1u) s_idx[pos0++] = (j0    ) * 64;
    if (mk & 2u) s_idx[pos0++] = (j0 + 1) * 64;
    if (mk & 4u) s_idx[pos0++] = (j0 + 2) * 64;
    if (mk & 8u) s_idx[pos0++] = (j0 + 3) * 64;
    __syncthreads();

    // ---- fused score + exp + sum (no max-subtract: |s| <= ~10, fp32-safe;
    //      validated in a prior passing round at rel_err 2.2e-7) ----
    float4 eiv = *(const float4*)&g_ei[blk * Hh];
    const float4* ej4 = (const float4*)g_ej;
    float lsum[4] = {};
    for (int k = tid; k < K; k += 256) {
        int j = s_idx[k] >> 6;
        float4 ejv = __ldg(&ej4[(b << 10) + j]);
        float s0 = eiv.x + ejv.x, s1 = eiv.y + ejv.y;
        float s2 = eiv.z + ejv.z, s3 = eiv.w + ejv.w;
        s0 = s0 > 0.0f ? s0 : NEG_SLOPE * s0;
        s1 = s1 > 0.0f ? s1 : NEG_SLOPE * s1;
        s2 = s2 > 0.0f ? s2 : NEG_SLOPE * s2;
        s3 = s3 > 0.0f ? s3 : NEG_SLOPE * s3;
        float w0 = __expf(s0), w1 = __expf(s1);
        float w2 = __expf(s2), w3 = __expf(s3);
        *(float4*)&s_w[k * Hh] = make_float4(w0, w1, w2, w3);
        lsum[0] += w0; lsum[1] += w1; lsum[2] += w2; lsum[3] += w3;
    }
#pragma unroll
    for (int off = 16; off > 0; off >>= 1)
#pragma unroll
        for (int h = 0; h < 4; h++)
            lsum[h] += __shfl_xor_sync(0xffffffffu, lsum[h], off);
    if (lane == 0)
#pragma unroll
        for (int h = 0; h < 4; h++) s_rsum[warp][h] = lsum[h];
    __syncthreads();   // orders s_w / s_idx writes before gather reads

    // ---- float4 gather: pos owns out floats [4pos,4pos+4), grp splits k ----
    const int pos = tid & 63;
    const int grp = tid >> 6;
    const int hh  = pos >> 4;            // head of this float4
    const float4* wx4 = (const float4*)(g_Wx + (size_t)b * (Nn * HD));
    float4 acc = make_float4(0.f, 0.f, 0.f, 0.f);
    int k = grp;
    for (; k + 12 < K; k += 16) {
        int oa = s_idx[k] + pos,     ob = s_idx[k + 4]  + pos;
        int oc = s_idx[k + 8] + pos, od = s_idx[k + 12] + pos;
        float wa = s_w[(k     ) * Hh + hh], wb = s_w[(k +  4) * Hh + hh];
        float wc = s_w[(k +  8) * Hh + hh], wd = s_w[(k + 12) * Hh + hh];
        float4 va = __ldg(&wx4[oa]);
        float4 vb = __ldg(&wx4[ob]);
        float4 vc = __ldg(&wx4[oc]);
        float4 vd = __ldg(&wx4[od]);
        acc.x = fmaf(wa, va.x, acc.x); acc.y = fmaf(wa, va.y, acc.y);
        acc.z = fmaf(wa, va.z, acc.z); acc.w = fmaf(wa, va.w, acc.w);
        acc.x = fmaf(wb, vb.x, acc.x); acc.y = fmaf(wb, vb.y, acc.y);
        acc.z = fmaf(wb, vb.z, acc.z); acc.w = fmaf(wb, vb.w, acc.w);
        acc.x = fmaf(wc, vc.x, acc.x); acc.y = fmaf(wc, vc.y, acc.y);
        acc.z = fmaf(wc, vc.z, acc.z); acc.w = fmaf(wc, vc.w, acc.w);
        acc.x = fmaf(wd, vd.x, acc.x); acc.y = fmaf(wd, vd.y, acc.y);
        acc.z = fmaf(wd, vd.z, acc.z); acc.w = fmaf(wd, vd.w, acc.w);
    }
    for (; k < K; k += 4) {
        int o = s_idx[k] + pos;
        float w = s_w[k * Hh + hh];
        float4 vv = __ldg(&wx4[o]);
        acc.x = fmaf(w, vv.x, acc.x); acc.y = fmaf(w, vv.y, acc.y);
        acc.z = fmaf(w, vv.z, acc.z); acc.w = fmaf(w, vv.w, acc.w);
    }
    *(float4*)&s_acc[grp][pos * 4] = acc;
    __syncthreads();

    // ---- cross-group reduce + normalize + store ----
    if (tid < 64) {
        const int h = tid >> 4;
        float4 r = *(float4*)&s_acc[0][tid * 4];
#pragma unroll
        for (int g = 1; g < 4; g++) {
            float4 t = *(float4*)&s_acc[g][tid * 4];
            r.x += t.x; r.y += t.y; r.z += t.z; r.w += t.w;
        }
        float tot = 0.0f;
#pragma unroll
        for (int w = 0; w < 8; w++) tot += s_rsum[w][h];
        float inv = 1.0f / tot;
        r.x *= inv; r.y *= inv; r.z *= inv; r.w *= inv;
        *(float4*)&out[(size_t)blk * HD + tid * 4] = r;
    }
}

// ---------------------------------------------------------------------------
extern "C" void kernel_launch(void* const* d_in, const int* in_sizes, int n_in,
                              void* d_out, int out_size) {
    const float *x = nullptr, *adj = nullptr, *W = nullptr, *a = nullptr;
    for (int i = 0; i < n_in; i++) {
        switch (in_sizes[i]) {
            case Bb * Nn * Cc:  x   = (const float*)d_in[i]; break;  // 2097152
            case Bb * Nn * Nn:  adj = (const float*)d_in[i]; break;  // 8388608
            case Cc * HD:       W   = (const float*)d_in[i]; break;  // 65536
            case Hh * 2 * Dd:   a   = (const float*)d_in[i]; break;  // 512
        }
    }
    float* out = (float*)d_out;

    dim3 ggrid(ROWS / 128, HD / 64);    // 64 x 4 = 256 blocks
    gemm_fused_k<<<ggrid, 256>>>(x, W, a);
    attn_k<<<ROWS, 256>>>(adj, out);
}